// round 17
// baseline (speedup 1.0000x reference)
#include <cuda_runtime.h>
#include <cuda_fp16.h>
#include <math.h>
#include <stdint.h>

#define LL 2048
#define BB 4
#define EE 512
#define HH 8
#define TT (LL*BB)

// ---------------- scratch ----------------
__device__ float  g_x0 [TT*EE];
__device__ float  g_proj[TT*EE];
__device__ float  g_x1 [TT*EE];
__device__ float  g_ff [TT*EE];
__device__ __half g_x0h [TT*EE];
__device__ __half g_qkvh[TT*3*EE];
__device__ __half g_atth[TT*EE];
__device__ __half g_x1h [TT*EE];
__device__ __half g_hh  [TT*2048];
__device__ __half g_wh  [3145728];   // in_w | out_w | w1 | w2
#define WOFF_IN  0
#define WOFF_OUT 786432
#define WOFF_W1  1048576
#define WOFF_W2  2097152

// ---------------- helpers ----------------
__device__ __forceinline__ float gelu_exact(float v) {
    return 0.5f * v * (1.0f + erff(v * 0.70710678118654752f));
}
__device__ __forceinline__ float ex2f(float x) {
    float y; asm("ex2.approx.f32 %0, %1;" : "=f"(y) : "f"(x)); return y;
}
__device__ __forceinline__ void cp16(void* smem_dst, const void* gsrc) {
    unsigned s = (unsigned)__cvta_generic_to_shared(smem_dst);
    asm volatile("cp.async.cg.shared.global [%0], [%1], 16;" :: "r"(s), "l"(gsrc));
}
#define CP_COMMIT() asm volatile("cp.async.commit_group;")
#define CP_WAIT1()  asm volatile("cp.async.wait_group 1;")

__device__ __forceinline__ uint4 ldsm4(const void* p) {
    unsigned s = (unsigned)__cvta_generic_to_shared(p);
    uint4 v;
    asm volatile("ldmatrix.sync.aligned.m8n8.x4.shared.b16 {%0,%1,%2,%3}, [%4];"
                 : "=r"(v.x), "=r"(v.y), "=r"(v.z), "=r"(v.w) : "r"(s));
    return v;
}
__device__ __forceinline__ uint4 ldsm4t(const void* p) {
    unsigned s = (unsigned)__cvta_generic_to_shared(p);
    uint4 v;
    asm volatile("ldmatrix.sync.aligned.m8n8.x4.trans.shared.b16 {%0,%1,%2,%3}, [%4];"
                 : "=r"(v.x), "=r"(v.y), "=r"(v.z), "=r"(v.w) : "r"(s));
    return v;
}
#define MMA16(c, a0,a1,a2,a3, b0,b1) asm volatile( \
    "mma.sync.aligned.m16n8k16.row.col.f32.f16.f16.f32 " \
    "{%0,%1,%2,%3}, {%4,%5,%6,%7}, {%8,%9}, {%0,%1,%2,%3};\n" \
    : "+f"((c)[0]), "+f"((c)[1]), "+f"((c)[2]), "+f"((c)[3]) \
    : "r"(a0), "r"(a1), "r"(a2), "r"(a3), "r"(b0), "r"(b1))

// ---------------- fused weight convert ----------------
__global__ void __launch_bounds__(256)
f2h_all(const float* __restrict__ w_in, const float* __restrict__ w_out,
        const float* __restrict__ w1, const float* __restrict__ w2,
        __half* __restrict__ dst) {
    int i = blockIdx.x * blockDim.x + threadIdx.x;
    if (i >= 786432) return;
    const float* src;
    int base;
    if (i < 196608)      { src = w_in;  base = 0;      }
    else if (i < 262144) { src = w_out; base = 196608; }
    else if (i < 524288) { src = w1;    base = 262144; }
    else                 { src = w2;    base = 524288; }
    float4 v = ((const float4*)src)[i - base];
    __half2 h0 = __floats2half2_rn(v.x, v.y);
    __half2 h1 = __floats2half2_rn(v.z, v.w);
    uint2 pk = { *(unsigned*)&h0, *(unsigned*)&h1 };
    ((uint2*)dst)[i] = pk;
}

// ---------------- PE add, vectorized ----------------
__global__ void __launch_bounds__(256)
pe_add_kernel(const float* __restrict__ x, float* __restrict__ out,
              __half* __restrict__ outh) {
    int i = blockIdx.x * blockDim.x + threadIdx.x;
    if (i >= TT*EE/4) return;
    int e4 = (i & (EE/4 - 1)) * 4;
    int b = (i / (EE/4)) & (BB - 1);
    float4 v = ((const float4*)x)[i];
    float pe[4];
#pragma unroll
    for (int j = 0; j < 4; j++) {
        int e = e4 + j;
        float ef = (e & 1) ? (float)(e + 1) : (float)e;
        float freq = __expf(-ef * (9.210340371976184f / 512.0f));
        float arg = (float)(b + 1) * freq;
        pe[j] = (e & 1) ? cosf(arg) : sinf(arg);
    }
    float4 o = {v.x + pe[0], v.y + pe[1], v.z + pe[2], v.w + pe[3]};
    ((float4*)out)[i] = o;
    __half2 h0 = __floats2half2_rn(o.x, o.y);
    __half2 h1 = __floats2half2_rn(o.z, o.w);
    uint2 pk = { *(unsigned*)&h0, *(unsigned*)&h1 };
    ((uint2*)outh)[i] = pk;
}

// ---------------- fp16 GEMM: CTA 128x256, warp 64x64, BK=32, 3-stage -------
// 256 thr = 8 warps (2m x 4n). smem stride 40 halves. A stage 10240 B,
// B stage 20480 B, stage total 30720 B, 3 stages = 92160 B.
#define HSTRIDE 40
#define STG_B   30720
#define A_HALF  5120          // halves in A stage (128*40)

template<int GELU, int HALF_OUT>
__global__ void __launch_bounds__(256, 1)
gemm_h(const __half* __restrict__ A, const __half* __restrict__ W,
       const float* __restrict__ bias, float* __restrict__ Cf,
       __half* __restrict__ Ch, int N, int K) {
    extern __shared__ __half smh[];

    const int tid = threadIdx.x, lane = tid & 31, warp = tid >> 5;
    const int g = lane >> 2, t = lane & 3;
    const int wm = warp >> 2, wn = warp & 3;
    const int bRow = blockIdx.y * 128, bCol = blockIdx.x * 256;
    const int lr = tid >> 1, ho = (tid & 1) * 16;
    const int l15 = lane & 15, lhi8 = (lane >> 4) << 3;
    const int bn = (lane & 7) + ((lane & 16) >> 1);
    const int bk = lane & 8;

    const __half* Ap = A + (size_t)(bRow + lr) * K + ho;
    const __half* Wp = W + (size_t)(bCol + tid) * K;

    float c[4][8][4];
#pragma unroll
    for (int ma = 0; ma < 4; ma++)
#pragma unroll
        for (int nf = 0; nf < 8; nf++)
#pragma unroll
            for (int q = 0; q < 4; q++) c[ma][nf][q] = 0.0f;

    const int KT = K >> 5;

    auto issue = [&](int s, int kt) {
        __half* as = smh + (s * STG_B) / 2;
        __half* bs = as + A_HALF;
        cp16(as + lr*HSTRIDE + ho,     Ap + kt*32);
        cp16(as + lr*HSTRIDE + ho + 8, Ap + kt*32 + 8);
        __half* bd = bs + tid*HSTRIDE;
        const __half* wp = Wp + kt*32;
        cp16(bd,      wp);
        cp16(bd + 8,  wp + 8);
        cp16(bd + 16, wp + 16);
        cp16(bd + 24, wp + 24);
    };

    issue(0, 0); CP_COMMIT();
    issue(1, 1); CP_COMMIT();
    CP_WAIT1();
    __syncthreads();

    for (int kt = 0; kt < KT; kt++) {
        const int cur = kt % 3;
        const __half* As = smh + (cur * STG_B) / 2;
        const __half* Bs = As + A_HALF;

#pragma unroll
        for (int kb = 0; kb < 2; kb++) {
            uint4 av[4];
#pragma unroll
            for (int ma = 0; ma < 4; ma++)
                av[ma] = ldsm4(&As[(wm*64 + ma*16 + l15)*HSTRIDE + kb*16 + lhi8]);
            unsigned bf[8][2];
#pragma unroll
            for (int np = 0; np < 4; np++) {
                uint4 bv = ldsm4(&Bs[(wn*64 + np*16 + bn)*HSTRIDE + kb*16 + bk]);
                bf[2*np][0]   = bv.x; bf[2*np][1]   = bv.y;
                bf[2*np+1][0] = bv.z; bf[2*np+1][1] = bv.w;
            }
#pragma unroll
            for (int ma = 0; ma < 4; ma++)
#pragma unroll
                for (int nf = 0; nf < 8; nf++)
                    MMA16(c[ma][nf], av[ma].x, av[ma].y, av[ma].z, av[ma].w,
                          bf[nf][0], bf[nf][1]);
        }

        if (kt + 2 < KT) issue((kt + 2) % 3, kt + 2);
        CP_COMMIT();
        CP_WAIT1();
        __syncthreads();
    }

#pragma unroll
    for (int ma = 0; ma < 4; ma++) {
#pragma unroll
        for (int nf = 0; nf < 8; nf++) {
            int col = bCol + wn*64 + nf*8 + 2*t;
            int row = bRow + wm*64 + ma*16 + g;
            float b0 = bias[col], b1 = bias[col+1];
            float v0 = c[ma][nf][0]+b0, v1 = c[ma][nf][1]+b1;
            float v2 = c[ma][nf][2]+b0, v3 = c[ma][nf][3]+b1;
            if (GELU) { v0=gelu_exact(v0); v1=gelu_exact(v1);
                        v2=gelu_exact(v2); v3=gelu_exact(v3); }
            if (HALF_OUT) {
                *(__half2*)&Ch[(size_t)row*N + col]     = __floats2half2_rn(v0, v1);
                *(__half2*)&Ch[(size_t)(row+8)*N + col] = __floats2half2_rn(v2, v3);
            } else {
                float2 p0 = {v0,v1}, p1 = {v2,v3};
                *(float2*)&Cf[(size_t)row*N + col]     = p0;
                *(float2*)&Cf[(size_t)(row+8)*N + col] = p1;
            }
        }
    }
}

// ---------------- fp16 flash attention (R13) ----------------
#define ASTRIDE 72
#define QKSCALE 0.18033688011112042f   // 0.125 * log2(e)
__global__ void __launch_bounds__(256)
attn_h(const __half* __restrict__ qkv, __half* __restrict__ outh) {
    extern __shared__ __half smh[];
    __half* Qs = smh;
    __half* Ks = smh + 128*ASTRIDE;
    __half* Vs = Ks + 2*64*ASTRIDE;

    const int tid = threadIdx.x, lane = tid & 31, warp = tid >> 5;
    const int g = lane >> 2, t = lane & 3;
    const int q0 = blockIdx.x * 128;
    const int b = blockIdx.y >> 3, h = blockIdx.y & 7;
    const int w16 = warp * 16;
    const int l15 = lane & 15, lhi8 = (lane >> 4) << 3;
    const int bn = (lane & 7) + ((lane & 16) >> 1);
    const int bk = lane & 8;
    const size_t qoff = h*64, koff = 512 + h*64, voff = 1024 + h*64;

    for (int i = tid; i < 128*8; i += 256) {
        int r = i >> 3, c = (i & 7) * 8;
        uint4 v = *(const uint4*)&qkv[((size_t)((q0+r)*BB + b))*1536 + qoff + c];
        __half2* hp = (__half2*)&v;
        uint4 w;
        unsigned* wp = (unsigned*)&w;
#pragma unroll
        for (int j = 0; j < 4; j++) {
            float2 f = __half22float2(hp[j]);
            __half2 sh = __floats2half2_rn(f.x * QKSCALE, f.y * QKSCALE);
            wp[j] = *(unsigned*)&sh;
        }
        *(uint4*)&Qs[r*ASTRIDE + c] = w;
    }

    auto issue = [&](int s, int kt) {
        int k0 = kt * 64;
#pragma unroll
        for (int j = 0; j < 4; j++) {
            int i = tid + j*256;
            int kv = i >> 9, r = (i >> 3) & 63, c = (i & 7) * 8;
            __half* dst = (kv ? Vs : Ks) + s*64*ASTRIDE + r*ASTRIDE + c;
            const __half* src = qkv + ((size_t)((k0+r)*BB + b))*1536 + (kv ? voff : koff) + c;
            cp16(dst, src);
        }
    };

    issue(0, 0); CP_COMMIT();

    float m_[2] = {-1e30f, -1e30f}, l_[2] = {0.0f, 0.0f};
    float o[8][4];
#pragma unroll
    for (int nf = 0; nf < 8; nf++)
#pragma unroll
        for (int q = 0; q < 4; q++) o[nf][q] = 0.0f;

    const int NT = LL/64;
    for (int kt = 0; kt < NT; kt++) {
        const int cur = kt & 1;
        if (kt + 1 < NT) issue(cur ^ 1, kt + 1);
        CP_COMMIT();
        CP_WAIT1();
        __syncthreads();

        const __half* Kc = Ks + cur*64*ASTRIDE;
        const __half* Vc = Vs + cur*64*ASTRIDE;

        float s_[8][4];
#pragma unroll
        for (int nf = 0; nf < 8; nf++)
#pragma unroll
            for (int q = 0; q < 4; q++) s_[nf][q] = 0.0f;

#pragma unroll
        for (int kb = 0; kb < 4; kb++) {
            uint4 av = ldsm4(&Qs[(w16 + l15)*ASTRIDE + kb*16 + lhi8]);
            unsigned bf[8][2];
#pragma unroll
            for (int np = 0; np < 4; np++) {
                uint4 bv = ldsm4(&Kc[(np*16 + bn)*ASTRIDE + kb*16 + bk]);
                bf[2*np][0]   = bv.x; bf[2*np][1]   = bv.y;
                bf[2*np+1][0] = bv.z; bf[2*np+1][1] = bv.w;
            }
#pragma unroll
            for (int nf = 0; nf < 8; nf++)
                MMA16(s_[nf], av.x, av.y, av.z, av.w, bf[nf][0], bf[nf][1]);
        }

        float sc[2];
#pragma unroll
        for (int hf = 0; hf < 2; hf++) {
            float mx = -1e30f;
#pragma unroll
            for (int nf = 0; nf < 8; nf++)
                mx = fmaxf(mx, fmaxf(s_[nf][2*hf], s_[nf][2*hf+1]));
            mx = fmaxf(mx, __shfl_xor_sync(0xffffffffu, mx, 1));
            mx = fmaxf(mx, __shfl_xor_sync(0xffffffffu, mx, 2));
            float mn = fmaxf(m_[hf], mx);
            sc[hf] = ex2f(m_[hf] - mn);
            float rs = 0.0f;
#pragma unroll
            for (int nf = 0; nf < 8; nf++) {
                s_[nf][2*hf]   = ex2f(s_[nf][2*hf]   - mn);
                s_[nf][2*hf+1] = ex2f(s_[nf][2*hf+1] - mn);
                rs += s_[nf][2*hf] + s_[nf][2*hf+1];
            }
            rs += __shfl_xor_sync(0xffffffffu, rs, 1);
            rs += __shfl_xor_sync(0xffffffffu, rs, 2);
            l_[hf] = l_[hf] * sc[hf] + rs;
            m_[hf] = mn;
        }
        bool need = (sc[0] != 1.0f) || (sc[1] != 1.0f);
        if (__any_sync(0xffffffffu, need)) {
#pragma unroll
            for (int nf = 0; nf < 8; nf++) {
                o[nf][0] *= sc[0]; o[nf][1] *= sc[0];
                o[nf][2] *= sc[1]; o[nf][3] *= sc[1];
            }
        }

#pragma unroll
        for (int kb = 0; kb < 4; kb++) {
            __half2 ah0 = __floats2half2_rn(s_[2*kb][0],   s_[2*kb][1]);
            __half2 ah1 = __floats2half2_rn(s_[2*kb][2],   s_[2*kb][3]);
            __half2 ah2 = __floats2half2_rn(s_[2*kb+1][0], s_[2*kb+1][1]);
            __half2 ah3 = __floats2half2_rn(s_[2*kb+1][2], s_[2*kb+1][3]);
            unsigned a0 = *(unsigned*)&ah0, a1 = *(unsigned*)&ah1;
            unsigned a2 = *(unsigned*)&ah2, a3 = *(unsigned*)&ah3;
            unsigned bf[8][2];
#pragma unroll
            for (int df = 0; df < 4; df++) {
                uint4 bv = ldsm4t(&Vc[(kb*16 + l15)*ASTRIDE + df*16 + lhi8]);
                bf[2*df][0]   = bv.x; bf[2*df][1]   = bv.y;
                bf[2*df+1][0] = bv.z; bf[2*df+1][1] = bv.w;
            }
#pragma unroll
            for (int nf = 0; nf < 8; nf++)
                MMA16(o[nf], a0, a1, a2, a3, bf[nf][0], bf[nf][1]);
        }
        __syncthreads();
    }

#pragma unroll
    for (int hf = 0; hf < 2; hf++) {
        float inv = 1.0f / l_[hf];
        int row = q0 + w16 + g + 8*hf;
        size_t base = ((size_t)row*BB + b)*512 + h*64;
#pragma unroll
        for (int nf = 0; nf < 8; nf++)
            *(__half2*)&outh[base + nf*8 + 2*t] =
                __floats2half2_rn(o[nf][2*hf]*inv, o[nf][2*hf+1]*inv);
    }
}

// ---------------- residual add + layernorm, vectorized ----------------
template<int WH>
__global__ void __launch_bounds__(128)
add_ln_kernel(const float* __restrict__ a, const float* __restrict__ r,
              const float* __restrict__ g, const float* __restrict__ beta,
              float* __restrict__ out, __half* __restrict__ outh) {
    __shared__ float red[4];
    int t = blockIdx.x;
    int tid = threadIdx.x;
    float4 va = ((const float4*)(a + (size_t)t*EE))[tid];
    float4 vr = ((const float4*)(r + (size_t)t*EE))[tid];
    float4 v = {va.x+vr.x, va.y+vr.y, va.z+vr.z, va.w+vr.w};

    float sum = v.x + v.y + v.z + v.w;
#pragma unroll
    for (int off = 16; off > 0; off >>= 1)
        sum += __shfl_xor_sync(0xffffffffu, sum, off);
    if ((tid & 31) == 0) red[tid >> 5] = sum;
    __syncthreads();
    float mu = (red[0] + red[1] + red[2] + red[3]) * (1.0f / 512.0f);
    __syncthreads();

    float4 d = {v.x-mu, v.y-mu, v.z-mu, v.w-mu};
    float sq = d.x*d.x + d.y*d.y + d.z*d.z + d.w*d.w;
#pragma unroll
    for (int off = 16; off > 0; off >>= 1)
        sq += __shfl_xor_sync(0xffffffffu, sq, off);
    if ((tid & 31) == 0) red[tid >> 5] = sq;
    __syncthreads();
    float rstd = rsqrtf((red[0]+red[1]+red[2]+red[3]) * (1.0f/512.0f) + 1e-5f);

    float4 gg = ((const float4*)g)[tid];
    float4 bb = ((const float4*)beta)[tid];
    float4 o = {d.x*rstd*gg.x + bb.x, d.y*rstd*gg.y + bb.y,
                d.z*rstd*gg.z + bb.z, d.w*rstd*gg.w + bb.w};
    ((float4*)(out + (size_t)t*EE))[tid] = o;
    if (WH) {
        __half2 h0 = __floats2half2_rn(o.x, o.y);
        __half2 h1 = __floats2half2_rn(o.z, o.w);
        uint2 pk = { *(unsigned*)&h0, *(unsigned*)&h1 };
        ((uint2*)(outh + (size_t)t*EE))[tid] = pk;
    }
}

// ---------------- launch ----------------
extern "C" void kernel_launch(void* const* d_in, const int* in_sizes, int n_in,
                              void* d_out, int out_size) {
    const float* x     = (const float*)d_in[0];
    const float* in_w  = (const float*)d_in[1];
    const float* in_b  = (const float*)d_in[2];
    const float* out_w = (const float*)d_in[3];
    const float* out_b = (const float*)d_in[4];
    const float* w1    = (const float*)d_in[5];
    const float* b1    = (const float*)d_in[6];
    const float* w2    = (const float*)d_in[7];
    const float* b2    = (const float*)d_in[8];
    const float* ln_g  = (const float*)d_in[9];
    const float* ln_b  = (const float*)d_in[10];
    float* out = (float*)d_out;

    float *x0, *proj, *x1, *ff;
    __half *x0h, *qkvh, *atth, *x1h, *hh, *wh;
    cudaGetSymbolAddress((void**)&x0,   g_x0);
    cudaGetSymbolAddress((void**)&proj, g_proj);
    cudaGetSymbolAddress((void**)&x1,   g_x1);
    cudaGetSymbolAddress((void**)&ff,   g_ff);
    cudaGetSymbolAddress((void**)&x0h,  g_x0h);
    cudaGetSymbolAddress((void**)&qkvh, g_qkvh);
    cudaGetSymbolAddress((void**)&atth, g_atth);
    cudaGetSymbolAddress((void**)&x1h,  g_x1h);
    cudaGetSymbolAddress((void**)&hh,   g_hh);
    cudaGetSymbolAddress((void**)&wh,   g_wh);

    const int gemm_smem = 3 * STG_B;                                   // 92160
    const int attn_smem = (128 + 4*64) * ASTRIDE * (int)sizeof(__half); // 55296
    cudaFuncSetAttribute(gemm_h<0,0>, cudaFuncAttributeMaxDynamicSharedMemorySize, gemm_smem);
    cudaFuncSetAttribute(gemm_h<0,1>, cudaFuncAttributeMaxDynamicSharedMemorySize, gemm_smem);
    cudaFuncSetAttribute(gemm_h<1,1>, cudaFuncAttributeMaxDynamicSharedMemorySize, gemm_smem);
    cudaFuncSetAttribute(attn_h, cudaFuncAttributeMaxDynamicSharedMemorySize, attn_smem);

    f2h_all<<<(786432 + 255)/256, 256>>>(in_w, out_w, w1, w2, wh);
    pe_add_kernel<<<(TT*EE/4 + 255)/256, 256>>>(x, x0, x0h);
    gemm_h<0,1><<<dim3(1536/256, TT/128), 256, gemm_smem>>>(x0h, wh + WOFF_IN, in_b, nullptr, qkvh, 1536, 512);
    attn_h<<<dim3(LL/128, BB*HH), 256, attn_smem>>>(qkvh, atth);
    gemm_h<0,0><<<dim3(512/256, TT/128), 256, gemm_smem>>>(atth, wh + WOFF_OUT, out_b, proj, nullptr, 512, 512);
    add_ln_kernel<1><<<TT, 128>>>(proj, x0, ln_g, ln_b, x1, x1h);
    gemm_h<1,1><<<dim3(2048/256, TT/128), 256, gemm_smem>>>(x1h, wh + WOFF_W1, b1, nullptr, hh, 2048, 512);
    gemm_h<0,0><<<dim3(512/256, TT/128), 256, gemm_smem>>>(hh, wh + WOFF_W2, b2, ff, nullptr, 512, 2048);
    add_ln_kernel<0><<<TT, 128>>>(ff, x1, ln_g, ln_b, out, nullptr);
}